// round 6
// baseline (speedup 1.0000x reference)
#include <cuda_runtime.h>
#include <math.h>

#define BB  8
#define SS  1024
#define HH  1024
#define NHH 16
#define HDD 64
#define KQKV (3 * HH)   // 3072

// Single scratch in plain GEMM-output layout: qkv[m][c], m = b*1024+s,
// c = head*192 + which*64 + d  (which: 0=Q, 1=K, 2=V) — exactly the
// reference's reshape(b, s, 16, 3, 64) flattening. 96 MB.
__device__ __align__(16) float g_qkv[(size_t)BB * SS * KQKV];

// ---------------------------------------------------------------------------
// Kernel 1: C[8192,3072] = A[8192,1024] @ W[1024,3072] + bias
// Textbook tiling: 64x64 block tile, BK=16, 256 threads, 4x4 per thread.
// ---------------------------------------------------------------------------
__global__ __launch_bounds__(256)
void qkv_gemm_kernel(const float* __restrict__ A,
                     const float* __restrict__ W,
                     const float* __restrict__ bias)
{
    __shared__ float sA[64][17];  // [m][k], pad to 17
    __shared__ float sB[16][65];  // [k][n], pad to 65

    const int tid = threadIdx.x;
    const int tx  = tid & 15;   // n-group
    const int ty  = tid >> 4;   // m-group
    const int rBase = blockIdx.y * 64;
    const int cBase = blockIdx.x * 64;

    float acc[4][4];
#pragma unroll
    for (int i = 0; i < 4; i++)
#pragma unroll
        for (int j = 0; j < 4; j++) acc[i][j] = 0.f;

    for (int kt = 0; kt < HH; kt += 16) {
        // A tile: 64 rows x 16 k = 1024 elements, 4 per thread
#pragma unroll
        for (int l = 0; l < 4; l++) {
            int idx = tid + l * 256;
            int m = idx >> 4;
            int k = idx & 15;
            sA[m][k] = A[(size_t)(rBase + m) * HH + kt + k];
        }
        // B tile: 16 rows x 64 n = 1024 elements, 4 per thread
#pragma unroll
        for (int l = 0; l < 4; l++) {
            int idx = tid + l * 256;
            int kr = idx >> 6;
            int n  = idx & 63;
            sB[kr][n] = W[(size_t)(kt + kr) * KQKV + cBase + n];
        }
        __syncthreads();

#pragma unroll
        for (int kk = 0; kk < 16; kk++) {
            float a[4], b[4];
#pragma unroll
            for (int i = 0; i < 4; i++) a[i] = sA[ty * 4 + i][kk];
#pragma unroll
            for (int j = 0; j < 4; j++) b[j] = sB[kk][tx * 4 + j];
#pragma unroll
            for (int i = 0; i < 4; i++)
#pragma unroll
                for (int j = 0; j < 4; j++)
                    acc[i][j] = fmaf(a[i], b[j], acc[i][j]);
        }
        __syncthreads();
    }

#pragma unroll
    for (int i = 0; i < 4; i++) {
        int m = rBase + ty * 4 + i;
#pragma unroll
        for (int j = 0; j < 4; j++) {
            int c = cBase + tx * 4 + j;
            g_qkv[(size_t)m * KQKV + c] = acc[i][j] + bias[c];
        }
    }
}

// ---------------------------------------------------------------------------
// Kernel 2: attention, full-row materialized softmax (no online rescaling).
// One block = (b, h, 32 query rows). 256 threads.
// Dynamic SMEM layout (floats):
//   Ss : [32][1032]  scores/probs            33024
//   Qs : [32][68]    query tile               2176
//   KVs: [64][68]    K-tile then V-tile       4352
//   red, red2: [32][8] reductions              512
//   msk: [1024] int                           1024
// total 41088 floats = 164352 bytes (needs opt-in > 48KB)
// ---------------------------------------------------------------------------
#define SS_STRIDE 1032
#define OFF_SS   0
#define OFF_QS   (OFF_SS  + 32 * SS_STRIDE)
#define OFF_KVS  (OFF_QS  + 32 * 68)
#define OFF_RED  (OFF_KVS + 64 * 68)
#define OFF_RED2 (OFF_RED + 32 * 8)
#define OFF_MSK  (OFF_RED2 + 32 * 8)
#define SMEM_ATTN_FLOATS (OFF_MSK + 1024)
#define SMEM_ATTN_BYTES  (SMEM_ATTN_FLOATS * 4)

__global__ __launch_bounds__(256)
void attn_kernel(const int* __restrict__ mask, float* __restrict__ out)
{
    extern __shared__ float sm[];
    float* Ss   = sm + OFF_SS;    // Ss[r][k] at r*SS_STRIDE + k
    float* Qs   = sm + OFF_QS;    // Qs[r][d] at r*68 + d
    float* KVs  = sm + OFF_KVS;   // KVs[row][d] at row*68 + d
    float* red  = sm + OFF_RED;   // [r*8 + part]
    float* red2 = sm + OFF_RED2;
    int*   msk  = (int*)(sm + OFF_MSK);

    const int tid = threadIdx.x;
    const int q0  = blockIdx.x * 32;
    const int h   = blockIdx.y;
    const int b   = blockIdx.z;

    const int r  = tid >> 3;   // 0..31: query row within tile
    const int g  = tid & 7;    // 0..7 : key-group / part / d-group

    const size_t rowBase = (size_t)b * SS;          // into qkv rows
    const int    colQ = h * 192;                    // Q columns
    const int    colK = h * 192 + 64;
    const int    colV = h * 192 + 128;

    // ---- Phase A: load Q tile (32x64) and the mask row ----
#pragma unroll
    for (int l = 0; l < 8; l++) {
        int idx = tid + l * 256;               // 0..2047
        int qr = idx >> 6;                     // 0..31
        int d  = idx & 63;
        Qs[qr * 68 + d] = g_qkv[(rowBase + q0 + qr) * KQKV + colQ + d];
    }
#pragma unroll
    for (int l = 0; l < 4; l++) {
        int idx = tid + l * 256;               // 0..1023
        msk[idx] = mask[b * SS + idx];
    }
    __syncthreads();

    // ---- Phase B: scores over all 1024 keys, 64-key tiles ----
    for (int kt = 0; kt < 16; kt++) {
        // load K tile: 64 rows x 64 d = 4096 elements, 16 per thread
#pragma unroll
        for (int l = 0; l < 16; l++) {
            int idx = tid + l * 256;           // 0..4095
            int kr = idx >> 6;                 // 0..63
            int d  = idx & 63;
            KVs[kr * 68 + d] = g_qkv[(rowBase + kt * 64 + kr) * KQKV + colK + d];
        }
        __syncthreads();

        float acc[8];
#pragma unroll
        for (int j = 0; j < 8; j++) acc[j] = 0.f;

        for (int d = 0; d < HDD; d++) {
            float qd = Qs[r * 68 + d];
#pragma unroll
            for (int j = 0; j < 8; j++) {
                int keyl = g + 8 * j;          // 0..63 across (g, j)
                acc[j] = fmaf(qd, KVs[keyl * 68 + d], acc[j]);
            }
        }

#pragma unroll
        for (int j = 0; j < 8; j++) {
            int keyl = g + 8 * j;
            int key  = kt * 64 + keyl;
            float s  = acc[j] * 8.0f;                  // * sqrt(64)
            if (msk[key] != 0) s = -10000.0f;          // reference mask semantics
            Ss[r * SS_STRIDE + key] = s;
        }
        __syncthreads();   // before next kt overwrites KVs
    }

    // ---- Phase C: softmax per row over 1024 stored scores ----
    // partial max over this thread's 128-key segment
    {
        float mx = -INFINITY;
        for (int k = g * 128; k < g * 128 + 128; k++)
            mx = fmaxf(mx, Ss[r * SS_STRIDE + k]);
        red[r * 8 + g] = mx;
    }
    __syncthreads();
    float rowmax = -INFINITY;
#pragma unroll
    for (int p = 0; p < 8; p++) rowmax = fmaxf(rowmax, red[r * 8 + p]);
    __syncthreads();   // all reads of red done before any reuse patterns below

    {
        float sum = 0.f;
        for (int k = g * 128; k < g * 128 + 128; k++) {
            float p = __expf(Ss[r * SS_STRIDE + k] - rowmax);
            Ss[r * SS_STRIDE + k] = p;
            sum += p;
        }
        red2[r * 8 + g] = sum;
    }
    __syncthreads();
    float rowsum = 0.f;
#pragma unroll
    for (int p = 0; p < 8; p++) rowsum += red2[r * 8 + p];
    // (no extra sync needed: red2 fully written before the barrier above,
    //  and Ss probs are also all visible now)

    // ---- Phase D: O[r][d] = sum_key P[r][key] * V[key][d] ----
    float o[8];
#pragma unroll
    for (int j = 0; j < 8; j++) o[j] = 0.f;

    for (int kt = 0; kt < 16; kt++) {
        __syncthreads();   // protect KVs from previous iteration's readers
#pragma unroll
        for (int l = 0; l < 16; l++) {
            int idx = tid + l * 256;
            int kr = idx >> 6;
            int d  = idx & 63;
            KVs[kr * 68 + d] = g_qkv[(rowBase + kt * 64 + kr) * KQKV + colV + d];
        }
        __syncthreads();

        for (int keyl = 0; keyl < 64; keyl++) {
            float p = Ss[r * SS_STRIDE + kt * 64 + keyl];
#pragma unroll
            for (int j = 0; j < 8; j++)
                o[j] = fmaf(p, KVs[keyl * 68 + g * 8 + j], o[j]);
        }
    }

    // ---- Phase E: normalize and write out[b][q0+r][h*64 + g*8 + j] ----
    {
        float inv = 1.0f / rowsum;
        size_t base = ((size_t)b * SS + q0 + r) * HH + h * HDD + g * 8;
#pragma unroll
        for (int j = 0; j < 8; j++)
            out[base + j] = o[j] * inv;
    }
}

// ---------------------------------------------------------------------------
// Resolve inputs by element count (robust to any metadata ordering):
//   hidden_states : 8388608 f32 | attention_mask: 8192 i32
//   w_qkv         : 3145728 f32 | b_qkv         : 3072 f32
// ---------------------------------------------------------------------------
extern "C" void kernel_launch(void* const* d_in, const int* in_sizes, int n_in,
                              void* d_out, int out_size)
{
    const float* hidden = nullptr;
    const int*   amask  = nullptr;
    const float* w_qkv  = nullptr;
    const float* b_qkv  = nullptr;

    for (int i = 0; i < n_in; i++) {
        switch (in_sizes[i]) {
            case 8388608: hidden = (const float*)d_in[i]; break;
            case 8192:    amask  = (const int*)  d_in[i]; break;
            case 3145728: w_qkv  = (const float*)d_in[i]; break;
            case 3072:    b_qkv  = (const float*)d_in[i]; break;
            default: break;
        }
    }
    if (!hidden) hidden = (const float*)d_in[0];
    if (!amask)  amask  = (const int*)  d_in[1];
    if (!w_qkv)  w_qkv  = (const float*)d_in[2];
    if (!b_qkv)  b_qkv  = (const float*)d_in[3];

    float* outp = (float*)d_out;

    dim3 g1(KQKV / 64, (BB * SS) / 64);    // (48, 128)
    qkv_gemm_kernel<<<g1, 256>>>(hidden, w_qkv, b_qkv);

    cudaFuncSetAttribute(attn_kernel,
                         cudaFuncAttributeMaxDynamicSharedMemorySize,
                         SMEM_ATTN_BYTES);
    dim3 g2(SS / 32, NHH, BB);             // (32, 16, 8)
    attn_kernel<<<g2, 256, SMEM_ATTN_BYTES>>>(amask, outp);

    (void)out_size;
}

// round 9
// speedup vs baseline: 1.0030x; 1.0030x over previous
#include <cuda_runtime.h>
#include <math.h>

#define BB  8
#define SS  1024
#define HH  1024
#define NHH 16
#define HDD 64
#define KQKV (3 * HH)   // 3072

// Scratch in plain GEMM-output layout: qkv[m][c], m = b*1024+s,
// c = head*192 + which*64 + d (0=Q,1=K,2=V) — verified correct in R6.
__device__ __align__(16) float g_qkv[(size_t)BB * SS * KQKV];

// ---------------------------------------------------------------------------
// Kernel 1: C[8192,3072] = A[8192,1024] @ W[1024,3072] + bias
// 128x128 tile, BK=16, 256 threads, 8x8 microtile. 4 LDS.128 : 64 FFMA.
// ---------------------------------------------------------------------------
__global__ __launch_bounds__(256, 2)
void qkv_gemm_kernel(const float* __restrict__ A,
                     const float* __restrict__ W,
                     const float* __restrict__ bias)
{
    __shared__ __align__(16) float sA[16][132];  // [k][m]
    __shared__ __align__(16) float sB[16][132];  // [k][n]

    const int tid = threadIdx.x;
    const int tx  = tid & 15;    // n-group (8 cols each)
    const int ty  = tid >> 4;    // m-group (8 rows each)
    const int rBase = blockIdx.y * 128;
    const int cBase = blockIdx.x * 128;

    // Load maps: A: 2 threads per row (m = tid>>1), k-chunks c,c+8 (c = 0 or 4)
    const int am = tid >> 1;          // 0..127
    const int ac = (tid & 1) * 4;     // 0 or 4
    // B: rows bk and bk+8, 4 cols per thread
    const int bk = tid >> 5;          // 0..7
    const int bn = (tid & 31) * 4;    // 0..124

    float acc[8][8];
#pragma unroll
    for (int i = 0; i < 8; i++)
#pragma unroll
        for (int j = 0; j < 8; j++) acc[i][j] = 0.f;

    const float* Arow = A + (size_t)(rBase + am) * HH;

    for (int kt = 0; kt < HH; kt += 16) {
        float4 a0 = *(const float4*)(Arow + kt + ac);
        float4 a1 = *(const float4*)(Arow + kt + ac + 8);
        sA[ac + 0][am] = a0.x;  sA[ac + 1][am] = a0.y;
        sA[ac + 2][am] = a0.z;  sA[ac + 3][am] = a0.w;
        sA[ac + 8][am] = a1.x;  sA[ac + 9][am] = a1.y;
        sA[ac +10][am] = a1.z;  sA[ac +11][am] = a1.w;

        *(float4*)&sB[bk][bn] =
            *(const float4*)(W + (size_t)(kt + bk) * KQKV + cBase + bn);
        *(float4*)&sB[bk + 8][bn] =
            *(const float4*)(W + (size_t)(kt + bk + 8) * KQKV + cBase + bn);
        __syncthreads();

#pragma unroll
        for (int kk = 0; kk < 16; kk++) {
            float4 A0 = *(float4*)&sA[kk][ty * 8];
            float4 A1 = *(float4*)&sA[kk][ty * 8 + 4];
            float4 B0 = *(float4*)&sB[kk][tx * 8];
            float4 B1 = *(float4*)&sB[kk][tx * 8 + 4];
            float a[8] = {A0.x, A0.y, A0.z, A0.w, A1.x, A1.y, A1.z, A1.w};
            float b[8] = {B0.x, B0.y, B0.z, B0.w, B1.x, B1.y, B1.z, B1.w};
#pragma unroll
            for (int i = 0; i < 8; i++)
#pragma unroll
                for (int j = 0; j < 8; j++)
                    acc[i][j] = fmaf(a[i], b[j], acc[i][j]);
        }
        __syncthreads();
    }

    float4 bb0 = *(const float4*)(bias + cBase + tx * 8);
    float4 bb1 = *(const float4*)(bias + cBase + tx * 8 + 4);
#pragma unroll
    for (int i = 0; i < 8; i++) {
        size_t m = (size_t)(rBase + ty * 8 + i);
        float4 o0, o1;
        o0.x = acc[i][0] + bb0.x;  o0.y = acc[i][1] + bb0.y;
        o0.z = acc[i][2] + bb0.z;  o0.w = acc[i][3] + bb0.w;
        o1.x = acc[i][4] + bb1.x;  o1.y = acc[i][5] + bb1.y;
        o1.z = acc[i][6] + bb1.z;  o1.w = acc[i][7] + bb1.w;
        *(float4*)(g_qkv + m * KQKV + cBase + tx * 8)     = o0;
        *(float4*)(g_qkv + m * KQKV + cBase + tx * 8 + 4) = o1;
    }
}

// ---------------------------------------------------------------------------
// Kernel 2: attention, materialized softmax (structure verified in R6),
// register-blocked + vectorized. One block = (b, h, 32 query rows), 256 thr.
// SMEM (floats):
//   Ss : [32][1032]  scores/probs
//   Qs : [32][68]
//   KVs: [128][68]   K-tile then V-tile (128-key tiles)
//   red, red2: [32][8]
//   msk: [1024] int
// ---------------------------------------------------------------------------
#define SS_STRIDE 1032
#define KT_KEYS   128
#define OFF_SS   0
#define OFF_QS   (OFF_SS  + 32 * SS_STRIDE)
#define OFF_KVS  (OFF_QS  + 32 * 68)
#define OFF_RED  (OFF_KVS + KT_KEYS * 68)
#define OFF_RED2 (OFF_RED + 32 * 8)
#define OFF_MSK  (OFF_RED2 + 32 * 8)
#define SMEM_ATTN_FLOATS (OFF_MSK + 1024)
#define SMEM_ATTN_BYTES  (SMEM_ATTN_FLOATS * 4)

__global__ __launch_bounds__(256)
void attn_kernel(const int* __restrict__ mask, float* __restrict__ out)
{
    extern __shared__ __align__(16) float sm[];
    float* Ss   = sm + OFF_SS;
    float* Qs   = sm + OFF_QS;
    float* KVs  = sm + OFF_KVS;
    float* red  = sm + OFF_RED;
    float* red2 = sm + OFF_RED2;
    int*   msk  = (int*)(sm + OFF_MSK);

    const int tid = threadIdx.x;
    const int q0  = blockIdx.x * 32;
    const int h   = blockIdx.y;
    const int b   = blockIdx.z;

    const size_t rowBase = (size_t)b * SS;
    const int colQ = h * 192;
    const int colK = colQ + 64;
    const int colV = colQ + 128;

    // ---- Phase A: Q tile (32x64, float4) + mask row ----
#pragma unroll
    for (int l = 0; l < 2; l++) {
        int idx = tid + l * 256;            // 0..511
        int qr = idx >> 4;
        int dc = (idx & 15) * 4;
        *(float4*)&Qs[qr * 68 + dc] =
            *(const float4*)(g_qkv + (rowBase + q0 + qr) * KQKV + colQ + dc);
    }
#pragma unroll
    for (int l = 0; l < 4; l++) {
        int idx = tid + l * 256;
        msk[idx] = mask[b * SS + idx];
    }
    __syncthreads();

    // ---- Phase B: scores, 128-key tiles, 4x4 microtile ----
    const int rg = tid >> 5;   // 0..7  : 4 query rows each
    const int kg = tid & 31;   // 0..31 : 4 keys each

    for (int kt = 0; kt < SS / KT_KEYS; kt++) {
        // K tile 128x64, 8 float4 per thread
#pragma unroll
        for (int l = 0; l < 8; l++) {
            int idx = tid + l * 256;        // 0..2047
            int kr = idx >> 4;              // 0..127
            int dc = (idx & 15) * 4;
            *(float4*)&KVs[kr * 68 + dc] =
                *(const float4*)(g_qkv + (rowBase + kt * KT_KEYS + kr) * KQKV + colK + dc);
        }
        __syncthreads();

        float acc[4][4];
#pragma unroll
        for (int i = 0; i < 4; i++)
#pragma unroll
            for (int j = 0; j < 4; j++) acc[i][j] = 0.f;

#pragma unroll
        for (int d4 = 0; d4 < HDD; d4 += 4) {
            float4 q[4], k[4];
#pragma unroll
            for (int i = 0; i < 4; i++) q[i] = *(float4*)&Qs[(4 * rg + i) * 68 + d4];
#pragma unroll
            for (int j = 0; j < 4; j++) k[j] = *(float4*)&KVs[(4 * kg + j) * 68 + d4];
#pragma unroll
            for (int i = 0; i < 4; i++)
#pragma unroll
                for (int j = 0; j < 4; j++) {
                    acc[i][j] = fmaf(q[i].x, k[j].x, acc[i][j]);
                    acc[i][j] = fmaf(q[i].y, k[j].y, acc[i][j]);
                    acc[i][j] = fmaf(q[i].z, k[j].z, acc[i][j]);
                    acc[i][j] = fmaf(q[i].w, k[j].w, acc[i][j]);
                }
        }

        const int keyBase = kt * KT_KEYS + 4 * kg;
        const int m0 = msk[keyBase + 0], m1 = msk[keyBase + 1];
        const int m2 = msk[keyBase + 2], m3 = msk[keyBase + 3];
#pragma unroll
        for (int i = 0; i < 4; i++) {
            float4 s;
            s.x = m0 ? -10000.0f : acc[i][0] * 8.0f;
            s.y = m1 ? -10000.0f : acc[i][1] * 8.0f;
            s.z = m2 ? -10000.0f : acc[i][2] * 8.0f;
            s.w = m3 ? -10000.0f : acc[i][3] * 8.0f;
            *(float4*)&Ss[(4 * rg + i) * SS_STRIDE + keyBase] = s;
        }
        __syncthreads();   // before next kt overwrites KVs
    }

    // ---- Phase C: softmax per row (two-pass, float4) ----
    const int r = tid >> 3;    // 0..31
    const int g = tid & 7;     // 0..7 : 128-key segment each
    const int segBase = r * SS_STRIDE + g * 128;
    {
        float mx = -INFINITY;
#pragma unroll 8
        for (int k4 = 0; k4 < 32; k4++) {
            float4 v = *(float4*)&Ss[segBase + k4 * 4];
            mx = fmaxf(mx, fmaxf(fmaxf(v.x, v.y), fmaxf(v.z, v.w)));
        }
        red[r * 8 + g] = mx;
    }
    __syncthreads();
    float rowmax = -INFINITY;
#pragma unroll
    for (int p = 0; p < 8; p++) rowmax = fmaxf(rowmax, red[r * 8 + p]);
    __syncthreads();
    {
        float sum = 0.f;
#pragma unroll 8
        for (int k4 = 0; k4 < 32; k4++) {
            float4 v = *(float4*)&Ss[segBase + k4 * 4];
            v.x = __expf(v.x - rowmax);
            v.y = __expf(v.y - rowmax);
            v.z = __expf(v.z - rowmax);
            v.w = __expf(v.w - rowmax);
            sum += (v.x + v.y) + (v.z + v.w);
            *(float4*)&Ss[segBase + k4 * 4] = v;
        }
        red2[r * 8 + g] = sum;
    }
    __syncthreads();
    {
        float rowsum = 0.f;
#pragma unroll
        for (int p = 0; p < 8; p++) rowsum += red2[r * 8 + p];
        if (g == 0) red[r] = 1.0f / rowsum;   // slot r; old max partial reads done
    }
    // visibility of red[r] guaranteed by the barriers in Phase D

    // ---- Phase D: PV, 128-key tiles, 2 rows x 4 cols per thread ----
    const int r2 = tid >> 4;          // 0..15 : rows 2*r2, 2*r2+1
    const int c4 = (tid & 15) * 4;    // d cols c4..c4+3
    float o[2][4];
#pragma unroll
    for (int i = 0; i < 2; i++)
#pragma unroll
        for (int j = 0; j < 4; j++) o[i][j] = 0.f;

    for (int kt = 0; kt < SS / KT_KEYS; kt++) {
        __syncthreads();   // KVs readers from previous iter done; red[] visible
#pragma unroll
        for (int l = 0; l < 8; l++) {
            int idx = tid + l * 256;
            int kr = idx >> 4;
            int dc = (idx & 15) * 4;
            *(float4*)&KVs[kr * 68 + dc] =
                *(const float4*)(g_qkv + (rowBase + kt * KT_KEYS + kr) * KQKV + colV + dc);
        }
        __syncthreads();

        const int pBase0 = (2 * r2) * SS_STRIDE + kt * KT_KEYS;
        const int pBase1 = pBase0 + SS_STRIDE;
#pragma unroll 4
        for (int key = 0; key < KT_KEYS; key += 4) {
            float4 p0 = *(float4*)&Ss[pBase0 + key];
            float4 p1 = *(float4*)&Ss[pBase1 + key];
            float4 v0 = *(float4*)&KVs[(key + 0) * 68 + c4];
            float4 v1 = *(float4*)&KVs[(key + 1) * 68 + c4];
            float4 v2 = *(float4*)&KVs[(key + 2) * 68 + c4];
            float4 v3 = *(float4*)&KVs[(key + 3) * 68 + c4];

            o[0][0] = fmaf(p0.x, v0.x, o[0][0]); o[0][1] = fmaf(p0.x, v0.y, o[0][1]);
            o[0][2] = fmaf(p0.x, v0.z, o[0][2]); o[0][3] = fmaf(p0.x, v0.w, o[0][3]);
            o[1][0] = fmaf(p1.x, v0.x, o[1][0]); o[1][1] = fmaf(p1.x, v0.y, o[1][1]);
            o[1][2] = fmaf(p1.x, v0.z, o[1][2]); o[1][3] = fmaf(p1.x, v0.w, o[1][3]);

            o[0][0] = fmaf(p0.y, v1.x, o[0][0]); o[0][1] = fmaf(p0.y, v1.y, o[0][1]);
            o[0][2] = fmaf(p0.y, v1.z, o[0][2]); o[0][3] = fmaf(p0.y, v1.w, o[0][3]);
            o[1][0] = fmaf(p1.y, v1.x, o[1][0]); o[1][1] = fmaf(p1.y, v1.y, o[1][1]);
            o[1][2] = fmaf(p1.y, v1.z, o[1][2]); o[1][3] = fmaf(p1.y, v1.w, o[1][3]);

            o[0][0] = fmaf(p0.z, v2.x, o[0][0]); o[0][1] = fmaf(p0.z, v2.y, o[0][1]);
            o[0][2] = fmaf(p0.z, v2.z, o[0][2]); o[0][3] = fmaf(p0.z, v2.w, o[0][3]);
            o[1][0] = fmaf(p1.z, v2.x, o[1][0]); o[1][1] = fmaf(p1.z, v2.y, o[1][1]);
            o[1][2] = fmaf(p1.z, v2.z, o[1][2]); o[1][3] = fmaf(p1.z, v2.w, o[1][3]);

            o[0][0] = fmaf(p0.w, v3.x, o[0][0]); o[0][1] = fmaf(p0.w, v3.y, o[0][1]);
            o[0][2] = fmaf(p0.w, v3.z, o[0][2]); o[0][3] = fmaf(p0.w, v3.w, o[0][3]);
            o[1][0] = fmaf(p1.w, v3.x, o[1][0]); o[1][1] = fmaf(p1.w, v3.y, o[1][1]);
            o[1][2] = fmaf(p1.w, v3.z, o[1][2]); o[1][3] = fmaf(p1.w, v3.w, o[1][3]);
        }
    }

    // ---- Phase E: normalize + write out[b][q0+row][h*64 + c4..] ----
#pragma unroll
    for (int i = 0; i < 2; i++) {
        int   row = 2 * r2 + i;
        float inv = red[row];
        float4 res;
        res.x = o[i][0] * inv;
        res.y = o[i][1] * inv;
        res.z = o[i][2] * inv;
        res.w = o[i][3] * inv;
        *(float4*)(out + ((size_t)b * SS + q0 + row) * HH + h * HDD + c4) = res;
    }
}

// ---------------------------------------------------------------------------
extern "C" void kernel_launch(void* const* d_in, const int* in_sizes, int n_in,
                              void* d_out, int out_size)
{
    const float* hidden = nullptr;
    const int*   amask  = nullptr;
    const float* w_qkv  = nullptr;
    const float* b_qkv  = nullptr;

    for (int i = 0; i < n_in; i++) {
        switch (in_sizes[i]) {
            case 8388608: hidden = (const float*)d_in[i]; break;
            case 8192:    amask  = (const int*)  d_in[i]; break;
            case 3145728: w_qkv  = (const float*)d_in[i]; break;
            case 3072:    b_qkv  = (const float*)d_in[i]; break;
            default: break;
        }
    }
    if (!hidden) hidden = (const float*)d_in[0];
    if (!amask)  amask  = (const int*)  d_in[1];
    if (!w_qkv)  w_qkv  = (const float*)d_in[2];
    if (!b_qkv)  b_qkv  = (const float*)d_in[3];

    float* outp = (float*)d_out;

    dim3 g1(KQKV / 128, (BB * SS) / 128);   // (24, 64)
    qkv_gemm_kernel<<<g1, 256>>>(hidden, w_qkv, b_qkv);

    static int smem_set = 0;
    if (!smem_set) {
        cudaFuncSetAttribute(attn_kernel,
                             cudaFuncAttributeMaxDynamicSharedMemorySize,
                             SMEM_ATTN_BYTES);
        smem_set = 1;
    }
    dim3 g2(SS / 32, NHH, BB);              // (32, 16, 8)
    attn_kernel<<<g2, 256, SMEM_ATTN_BYTES>>>(amask, outp);

    (void)out_size;
}

// round 10
// speedup vs baseline: 1.9872x; 1.9813x over previous
#include <cuda_runtime.h>
#include <math.h>

#define BB  8
#define SS  1024
#define HH  1024
#define NHH 16
#define HDD 64
#define KQKV (3 * HH)   // 3072

// Scratch in plain GEMM-output layout: qkv[m][c], m = b*1024+s,
// c = head*192 + which*64 + d (0=Q,1=K,2=V) — verified correct since R6.
__device__ __align__(16) float g_qkv[(size_t)BB * SS * KQKV];

// ---------------------------------------------------------------------------
// Kernel 1: C[8192,3072] = A[8192,1024] @ W[1024,3072] + bias
// 128x128 tile, BK=16, 256 threads, 8x8 microtile.
// B columns per thread: {4tx..4tx+3, 64+4tx..64+4tx+3} -> conflict-free sB.
// ---------------------------------------------------------------------------
__global__ __launch_bounds__(256, 2)
void qkv_gemm_kernel(const float* __restrict__ A,
                     const float* __restrict__ W,
                     const float* __restrict__ bias)
{
    __shared__ __align__(16) float sA[16][132];  // [k][m]
    __shared__ __align__(16) float sB[16][132];  // [k][n]

    const int tid = threadIdx.x;
    const int tx  = tid & 15;    // n-group
    const int ty  = tid >> 4;    // m-group (8 rows)
    const int rBase = blockIdx.y * 128;
    const int cBase = blockIdx.x * 128;

    const int am = tid >> 1;          // 0..127
    const int ac = (tid & 1) * 4;     // 0 or 4
    const int bk = tid >> 5;          // 0..7
    const int bn = (tid & 31) * 4;    // 0..124

    float acc[8][8];
#pragma unroll
    for (int i = 0; i < 8; i++)
#pragma unroll
        for (int j = 0; j < 8; j++) acc[i][j] = 0.f;

    const float* Arow = A + (size_t)(rBase + am) * HH;

    for (int kt = 0; kt < HH; kt += 16) {
        float4 a0 = *(const float4*)(Arow + kt + ac);
        float4 a1 = *(const float4*)(Arow + kt + ac + 8);
        sA[ac + 0][am] = a0.x;  sA[ac + 1][am] = a0.y;
        sA[ac + 2][am] = a0.z;  sA[ac + 3][am] = a0.w;
        sA[ac + 8][am] = a1.x;  sA[ac + 9][am] = a1.y;
        sA[ac +10][am] = a1.z;  sA[ac +11][am] = a1.w;

        *(float4*)&sB[bk][bn] =
            *(const float4*)(W + (size_t)(kt + bk) * KQKV + cBase + bn);
        *(float4*)&sB[bk + 8][bn] =
            *(const float4*)(W + (size_t)(kt + bk + 8) * KQKV + cBase + bn);
        __syncthreads();

#pragma unroll
        for (int kk = 0; kk < 16; kk++) {
            float4 A0 = *(float4*)&sA[kk][ty * 8];
            float4 A1 = *(float4*)&sA[kk][ty * 8 + 4];
            float4 B0 = *(float4*)&sB[kk][tx * 4];        // cols 4tx..4tx+3
            float4 B1 = *(float4*)&sB[kk][64 + tx * 4];   // cols 64+4tx..
            float a[8] = {A0.x, A0.y, A0.z, A0.w, A1.x, A1.y, A1.z, A1.w};
            float b[8] = {B0.x, B0.y, B0.z, B0.w, B1.x, B1.y, B1.z, B1.w};
#pragma unroll
            for (int i = 0; i < 8; i++)
#pragma unroll
                for (int j = 0; j < 8; j++)
                    acc[i][j] = fmaf(a[i], b[j], acc[i][j]);
        }
        __syncthreads();
    }

    float4 bb0 = *(const float4*)(bias + cBase + tx * 4);
    float4 bb1 = *(const float4*)(bias + cBase + 64 + tx * 4);
#pragma unroll
    for (int i = 0; i < 8; i++) {
        size_t m = (size_t)(rBase + ty * 8 + i);
        float4 o0, o1;
        o0.x = acc[i][0] + bb0.x;  o0.y = acc[i][1] + bb0.y;
        o0.z = acc[i][2] + bb0.z;  o0.w = acc[i][3] + bb0.w;
        o1.x = acc[i][4] + bb1.x;  o1.y = acc[i][5] + bb1.y;
        o1.z = acc[i][6] + bb1.z;  o1.w = acc[i][7] + bb1.w;
        *(float4*)(g_qkv + m * KQKV + cBase + tx * 4)      = o0;
        *(float4*)(g_qkv + m * KQKV + cBase + 64 + tx * 4) = o1;
    }
}

// ---------------------------------------------------------------------------
// Kernel 2: attention, materialized softmax. One block = (b, h, 32 q-rows),
// 256 threads. All SMEM access patterns conflict-free (bank-verified).
// SMEM (floats):
//   Ss : [32][1032]  scores/probs
//   Qs : [32][68]
//   KVs: [128][68]   K tiles (64 rows used) then V tiles (128 rows)
//   red, red2: [32][8]
//   msk: [1024] int
// ---------------------------------------------------------------------------
#define SS_STRIDE 1032
#define OFF_SS   0
#define OFF_QS   (OFF_SS  + 32 * SS_STRIDE)
#define OFF_KVS  (OFF_QS  + 32 * 68)
#define OFF_RED  (OFF_KVS + 128 * 68)
#define OFF_RED2 (OFF_RED + 32 * 8)
#define OFF_MSK  (OFF_RED2 + 32 * 8)
#define SMEM_ATTN_FLOATS (OFF_MSK + 1024)
#define SMEM_ATTN_BYTES  (SMEM_ATTN_FLOATS * 4)

__global__ __launch_bounds__(256)
void attn_kernel(const int* __restrict__ mask, float* __restrict__ out)
{
    extern __shared__ __align__(16) float sm[];
    float* Ss   = sm + OFF_SS;
    float* Qs   = sm + OFF_QS;
    float* KVs  = sm + OFF_KVS;
    float* red  = sm + OFF_RED;
    float* red2 = sm + OFF_RED2;
    int*   msk  = (int*)(sm + OFF_MSK);

    const int tid = threadIdx.x;
    const int q0  = blockIdx.x * 32;
    const int h   = blockIdx.y;
    const int b   = blockIdx.z;

    const size_t rowBase = (size_t)b * SS;
    const int colQ = h * 192;
    const int colK = colQ + 64;
    const int colV = colQ + 128;

    // ---- Phase A: Q tile (32x64, float4) + mask row ----
#pragma unroll
    for (int l = 0; l < 2; l++) {
        int idx = tid + l * 256;
        int qr = idx >> 4;
        int dc = (idx & 15) * 4;
        *(float4*)&Qs[qr * 68 + dc] =
            *(const float4*)(g_qkv + (rowBase + q0 + qr) * KQKV + colQ + dc);
    }
#pragma unroll
    for (int l = 0; l < 4; l++) {
        int idx = tid + l * 256;
        msk[idx] = mask[b * SS + idx];
    }
    __syncthreads();

    // ---- Phase B: scores, 64-key tiles, interleaved key ownership ----
    // warp rg = tid>>5 owns rows 4rg..4rg+3; lane kg owns keys kg, kg+32.
    // K-read banks: lane kg -> 68*kg ≡ 4*kg (mod 32); quarter-warps span all
    // 32 banks -> conflict-free LDS.128 at the 4-wavefront minimum.
    const int rg = tid >> 5;
    const int kg = tid & 31;

    for (int kt = 0; kt < SS / 64; kt++) {
        // K tile 64x64: 4 float4 per thread
#pragma unroll
        for (int l = 0; l < 4; l++) {
            int idx = tid + l * 256;        // 0..1023
            int kr = idx >> 4;              // 0..63
            int dc = (idx & 15) * 4;
            *(float4*)&KVs[kr * 68 + dc] =
                *(const float4*)(g_qkv + (rowBase + kt * 64 + kr) * KQKV + colK + dc);
        }
        __syncthreads();

        float acc[4][2];
#pragma unroll
        for (int i = 0; i < 4; i++) { acc[i][0] = 0.f; acc[i][1] = 0.f; }

#pragma unroll
        for (int d4 = 0; d4 < HDD; d4 += 4) {
            float4 k0 = *(float4*)&KVs[kg * 68 + d4];
            float4 k1 = *(float4*)&KVs[(kg + 32) * 68 + d4];
#pragma unroll
            for (int i = 0; i < 4; i++) {
                float4 q = *(float4*)&Qs[(4 * rg + i) * 68 + d4];
                acc[i][0] = fmaf(q.x, k0.x, acc[i][0]);
                acc[i][0] = fmaf(q.y, k0.y, acc[i][0]);
                acc[i][0] = fmaf(q.z, k0.z, acc[i][0]);
                acc[i][0] = fmaf(q.w, k0.w, acc[i][0]);
                acc[i][1] = fmaf(q.x, k1.x, acc[i][1]);
                acc[i][1] = fmaf(q.y, k1.y, acc[i][1]);
                acc[i][1] = fmaf(q.z, k1.z, acc[i][1]);
                acc[i][1] = fmaf(q.w, k1.w, acc[i][1]);
            }
        }

        const int key0 = kt * 64 + kg;
        const int m0 = msk[key0];
        const int m1 = msk[key0 + 32];
#pragma unroll
        for (int i = 0; i < 4; i++) {
            int rb = (4 * rg + i) * SS_STRIDE;
            Ss[rb + key0]      = m0 ? -10000.0f : acc[i][0] * 8.0f;
            Ss[rb + key0 + 32] = m1 ? -10000.0f : acc[i][1] * 8.0f;
        }
        __syncthreads();   // before next kt overwrites KVs
    }

    // ---- Phase C: softmax, interleaved segments (conflict-free) ----
    // row r = tid>>3; thread g = tid&7 owns float4s at g*4 + 32*t.
    const int r = tid >> 3;
    const int g = tid & 7;
    const int rowOff = r * SS_STRIDE + g * 4;
    {
        float mx = -INFINITY;
#pragma unroll 8
        for (int t = 0; t < 32; t++) {
            float4 v = *(float4*)&Ss[rowOff + t * 32];
            mx = fmaxf(mx, fmaxf(fmaxf(v.x, v.y), fmaxf(v.z, v.w)));
        }
        red[r * 8 + g] = mx;
    }
    __syncthreads();
    float rowmax = -INFINITY;
#pragma unroll
    for (int p = 0; p < 8; p++) rowmax = fmaxf(rowmax, red[r * 8 + p]);
    __syncthreads();
    {
        float sum = 0.f;
#pragma unroll 8
        for (int t = 0; t < 32; t++) {
            float4 v = *(float4*)&Ss[rowOff + t * 32];
            v.x = __expf(v.x - rowmax);
            v.y = __expf(v.y - rowmax);
            v.z = __expf(v.z - rowmax);
            v.w = __expf(v.w - rowmax);
            sum += (v.x + v.y) + (v.z + v.w);
            *(float4*)&Ss[rowOff + t * 32] = v;
        }
        red2[r * 8 + g] = sum;
    }
    __syncthreads();
    {
        float rowsum = 0.f;
#pragma unroll
        for (int p = 0; p < 8; p++) rowsum += red2[r * 8 + p];
        if (g == 0) red[r] = 1.0f / rowsum;
    }
    // red[r] visibility guaranteed by Phase D barriers.

    // ---- Phase D: PV, 128-key tiles, 2 rows x 4 cols per thread ----
    const int r2 = tid >> 4;
    const int c4 = (tid & 15) * 4;
    float o[2][4];
#pragma unroll
    for (int i = 0; i < 2; i++)
#pragma unroll
        for (int j = 0; j < 4; j++) o[i][j] = 0.f;

    for (int kt = 0; kt < SS / 128; kt++) {
        __syncthreads();
#pragma unroll
        for (int l = 0; l < 8; l++) {
            int idx = tid + l * 256;
            int kr = idx >> 4;
            int dc = (idx & 15) * 4;
            *(float4*)&KVs[kr * 68 + dc] =
                *(const float4*)(g_qkv + (rowBase + kt * 128 + kr) * KQKV + colV + dc);
        }
        __syncthreads();

        const int pBase0 = (2 * r2) * SS_STRIDE + kt * 128;
        const int pBase1 = pBase0 + SS_STRIDE;
#pragma unroll 4
        for (int key = 0; key < 128; key += 4) {
            float4 p0 = *(float4*)&Ss[pBase0 + key];
            float4 p1 = *(float4*)&Ss[pBase1 + key];
            float4 v0 = *(float4*)&KVs[(key + 0) * 68 + c4];
            float4 v1 = *(float4*)&KVs[(key + 1) * 68 + c4];
            float4 v2 = *(float4*)&KVs[(key + 2) * 68 + c4];
            float4 v3 = *(float4*)&KVs[(key + 3) * 68 + c4];

            o[0][0] = fmaf(p0.x, v0.x, o[0][0]); o[0][1] = fmaf(p0.x, v0.y, o[0][1]);
            o[0][2] = fmaf(p0.x, v0.z, o[0][2]); o[0][3] = fmaf(p0.x, v0.w, o[0][3]);
            o[1][0] = fmaf(p1.x, v0.x, o[1][0]); o[1][1] = fmaf(p1.x, v0.y, o[1][1]);
            o[1][2] = fmaf(p1.x, v0.z, o[1][2]); o[1][3] = fmaf(p1.x, v0.w, o[1][3]);

            o[0][0] = fmaf(p0.y, v1.x, o[0][0]); o[0][1] = fmaf(p0.y, v1.y, o[0][1]);
            o[0][2] = fmaf(p0.y, v1.z, o[0][2]); o[0][3] = fmaf(p0.y, v1.w, o[0][3]);
            o[1][0] = fmaf(p1.y, v1.x, o[1][0]); o[1][1] = fmaf(p1.y, v1.y, o[1][1]);
            o[1][2] = fmaf(p1.y, v1.z, o[1][2]); o[1][3] = fmaf(p1.y, v1.w, o[1][3]);

            o[0][0] = fmaf(p0.z, v2.x, o[0][0]); o[0][1] = fmaf(p0.z, v2.y, o[0][1]);
            o[0][2] = fmaf(p0.z, v2.z, o[0][2]); o[0][3] = fmaf(p0.z, v2.w, o[0][3]);
            o[1][0] = fmaf(p1.z, v2.x, o[1][0]); o[1][1] = fmaf(p1.z, v2.y, o[1][1]);
            o[1][2] = fmaf(p1.z, v2.z, o[1][2]); o[1][3] = fmaf(p1.z, v2.w, o[1][3]);

            o[0][0] = fmaf(p0.w, v3.x, o[0][0]); o[0][1] = fmaf(p0.w, v3.y, o[0][1]);
            o[0][2] = fmaf(p0.w, v3.z, o[0][2]); o[0][3] = fmaf(p0.w, v3.w, o[0][3]);
            o[1][0] = fmaf(p1.w, v3.x, o[1][0]); o[1][1] = fmaf(p1.w, v3.y, o[1][1]);
            o[1][2] = fmaf(p1.w, v3.z, o[1][2]); o[1][3] = fmaf(p1.w, v3.w, o[1][3]);
        }
    }

    // ---- Phase E: normalize + write out[b][q0+row][h*64 + c4..] ----
#pragma unroll
    for (int i = 0; i < 2; i++) {
        int   row = 2 * r2 + i;
        float inv = red[row];
        float4 res;
        res.x = o[i][0] * inv;
        res.y = o[i][1] * inv;
        res.z = o[i][2] * inv;
        res.w = o[i][3] * inv;
        *(float4*)(out + ((size_t)b * SS + q0 + row) * HH + h * HDD + c4) = res;
    }
}

// ---------------------------------------------------------------------------
extern "C" void kernel_launch(void* const* d_in, const int* in_sizes, int n_in,
                              void* d_out, int out_size)
{
    const float* hidden = nullptr;
    const int*   amask  = nullptr;
    const float* w_qkv  = nullptr;
    const float* b_qkv  = nullptr;

    for (int i = 0; i < n_in; i++) {
        switch (in_sizes[i]) {
            case 8388608: hidden = (const float*)d_in[i]; break;
            case 8192:    amask  = (const int*)  d_in[i]; break;
            case 3145728: w_qkv  = (const float*)d_in[i]; break;
            case 3072:    b_qkv  = (const float*)d_in[i]; break;
            default: break;
        }
    }
    if (!hidden) hidden = (const float*)d_in[0];
    if (!amask)  amask  = (const int*)  d_in[1];
    if (!w_qkv)  w_qkv  = (const float*)d_in[2];
    if (!b_qkv)  b_qkv  = (const float*)d_in[3];

    float* outp = (float*)d_out;

    dim3 g1(KQKV / 128, (BB * SS) / 128);   // (24, 64)
    qkv_gemm_kernel<<<g1, 256>>>(hidden, w_qkv, b_qkv);

    static int smem_set = 0;
    if (!smem_set) {
        cudaFuncSetAttribute(attn_kernel,
                             cudaFuncAttributeMaxDynamicSharedMemorySize,
                             SMEM_ATTN_BYTES);
        smem_set = 1;
    }
    dim3 g2(SS / 32, NHH, BB);              // (32, 16, 8)
    attn_kernel<<<g2, 256, SMEM_ATTN_BYTES>>>(amask, outp);

    (void)out_size;
}

// round 11
// speedup vs baseline: 2.1352x; 1.0745x over previous
#include <cuda_runtime.h>
#include <math.h>

#define BB  8
#define SS  1024
#define HH  1024
#define NHH 16
#define HDD 64
#define KQKV (3 * HH)   // 3072

// Scratch in plain GEMM-output layout: qkv[m][c], m = b*1024+s,
// c = head*192 + which*64 + d (0=Q,1=K,2=V) — verified correct since R6.
__device__ __align__(16) float g_qkv[(size_t)BB * SS * KQKV];

// ---------------------------------------------------------------------------
// Kernel 1 (unchanged from R10, verified): C = A @ W + bias
// 128x128 tile, BK=16, 256 threads, 8x8 microtile, conflict-free smem.
// ---------------------------------------------------------------------------
__global__ __launch_bounds__(256, 2)
void qkv_gemm_kernel(const float* __restrict__ A,
                     const float* __restrict__ W,
                     const float* __restrict__ bias)
{
    __shared__ __align__(16) float sA[16][132];  // [k][m]
    __shared__ __align__(16) float sB[16][132];  // [k][n]

    const int tid = threadIdx.x;
    const int tx  = tid & 15;
    const int ty  = tid >> 4;
    const int rBase = blockIdx.y * 128;
    const int cBase = blockIdx.x * 128;

    const int am = tid >> 1;
    const int ac = (tid & 1) * 4;
    const int bk = tid >> 5;
    const int bn = (tid & 31) * 4;

    float acc[8][8];
#pragma unroll
    for (int i = 0; i < 8; i++)
#pragma unroll
        for (int j = 0; j < 8; j++) acc[i][j] = 0.f;

    const float* Arow = A + (size_t)(rBase + am) * HH;

    for (int kt = 0; kt < HH; kt += 16) {
        float4 a0 = *(const float4*)(Arow + kt + ac);
        float4 a1 = *(const float4*)(Arow + kt + ac + 8);
        sA[ac + 0][am] = a0.x;  sA[ac + 1][am] = a0.y;
        sA[ac + 2][am] = a0.z;  sA[ac + 3][am] = a0.w;
        sA[ac + 8][am] = a1.x;  sA[ac + 9][am] = a1.y;
        sA[ac +10][am] = a1.z;  sA[ac +11][am] = a1.w;

        *(float4*)&sB[bk][bn] =
            *(const float4*)(W + (size_t)(kt + bk) * KQKV + cBase + bn);
        *(float4*)&sB[bk + 8][bn] =
            *(const float4*)(W + (size_t)(kt + bk + 8) * KQKV + cBase + bn);
        __syncthreads();

#pragma unroll
        for (int kk = 0; kk < 16; kk++) {
            float4 A0 = *(float4*)&sA[kk][ty * 8];
            float4 A1 = *(float4*)&sA[kk][ty * 8 + 4];
            float4 B0 = *(float4*)&sB[kk][tx * 4];
            float4 B1 = *(float4*)&sB[kk][64 + tx * 4];
            float a[8] = {A0.x, A0.y, A0.z, A0.w, A1.x, A1.y, A1.z, A1.w};
            float b[8] = {B0.x, B0.y, B0.z, B0.w, B1.x, B1.y, B1.z, B1.w};
#pragma unroll
            for (int i = 0; i < 8; i++)
#pragma unroll
                for (int j = 0; j < 8; j++)
                    acc[i][j] = fmaf(a[i], b[j], acc[i][j]);
        }
        __syncthreads();
    }

    float4 bb0 = *(const float4*)(bias + cBase + tx * 4);
    float4 bb1 = *(const float4*)(bias + cBase + 64 + tx * 4);
#pragma unroll
    for (int i = 0; i < 8; i++) {
        size_t m = (size_t)(rBase + ty * 8 + i);
        float4 o0, o1;
        o0.x = acc[i][0] + bb0.x;  o0.y = acc[i][1] + bb0.y;
        o0.z = acc[i][2] + bb0.z;  o0.w = acc[i][3] + bb0.w;
        o1.x = acc[i][4] + bb1.x;  o1.y = acc[i][5] + bb1.y;
        o1.z = acc[i][6] + bb1.z;  o1.w = acc[i][7] + bb1.w;
        *(float4*)(g_qkv + m * KQKV + cBase + tx * 4)      = o0;
        *(float4*)(g_qkv + m * KQKV + cBase + 64 + tx * 4) = o1;
    }
}

// ---------------------------------------------------------------------------
// Kernel 2: flash-style attention with online softmax (no materialized Ss).
// Block = (b, h, 64 query rows), 256 threads = 8 warps; warp w owns rows
// 8w..8w+7 for the whole pipeline. 16 tiles of 64 keys.
// SMEM (stride-68 rows, all patterns bank-verified conflict-free):
//   Qs[64][68], Ks[64][68], Vs[64][68], Ps[64][68], msk[1024]  -> 73.7 KB
//   => 3 CTAs/SM (24 warps).
// ---------------------------------------------------------------------------
#define OFF_Q 0
#define OFF_K (OFF_Q + 64 * 68)
#define OFF_V (OFF_K + 64 * 68)
#define OFF_P (OFF_V + 64 * 68)
#define OFF_M (OFF_P + 64 * 68)
#define SMEM_ATTN_FLOATS (OFF_M + 1024)
#define SMEM_ATTN_BYTES  (SMEM_ATTN_FLOATS * 4)

__global__ __launch_bounds__(256, 3)
void attn_kernel(const int* __restrict__ mask, float* __restrict__ out)
{
    extern __shared__ __align__(16) float sm[];
    float* Qs = sm + OFF_Q;
    float* Ks = sm + OFF_K;
    float* Vs = sm + OFF_V;
    float* Ps = sm + OFF_P;
    int*   msk = (int*)(sm + OFF_M);

    const int tid  = threadIdx.x;
    const int w    = tid >> 5;    // warp 0..7, owns rows 8w..8w+7
    const int lane = tid & 31;
    const int q0   = blockIdx.x * 64;
    const int h    = blockIdx.y;
    const int b    = blockIdx.z;

    const size_t rowBase = (size_t)b * SS;
    const int colQ = h * 192;
    const int colK = colQ + 64;
    const int colV = colQ + 128;

    // score mapping: lane kg owns keys kg, kg+32 of each tile
    const int kg = lane;
    // PV mapping: lane = (row_sub, d-group); d cols = dg*4 + 16c + j
    const int rs = lane >> 2;    // 0..7
    const int dg = lane & 3;     // 0..3

    // ---- load Q tile (64x64, 4 float4/thread) + mask row ----
#pragma unroll
    for (int l = 0; l < 4; l++) {
        int idx = tid + l * 256;            // 0..1023
        int qr = idx >> 4;
        int dc = (idx & 15) * 4;
        *(float4*)&Qs[qr * 68 + dc] =
            *(const float4*)(g_qkv + (rowBase + q0 + qr) * KQKV + colQ + dc);
    }
#pragma unroll
    for (int l = 0; l < 4; l++) {
        int idx = tid + l * 256;
        msk[idx] = mask[b * SS + idx];
    }

    float m_i[8], l_i[8], o[16];
#pragma unroll
    for (int i = 0; i < 8; i++) { m_i[i] = -INFINITY; l_i[i] = 0.f; }
#pragma unroll
    for (int j = 0; j < 16; j++) o[j] = 0.f;

    for (int kt = 0; kt < SS / 64; kt++) {
        __syncthreads();   // prev-tile K/V readers done; 1st iter: Q/msk visible

        // load K,V tiles (64x64 each, 4 float4/thread per tensor)
#pragma unroll
        for (int l = 0; l < 4; l++) {
            int idx = tid + l * 256;
            int kr = idx >> 4;
            int dc = (idx & 15) * 4;
            const float* src = g_qkv + (rowBase + kt * 64 + kr) * KQKV;
            *(float4*)&Ks[kr * 68 + dc] = *(const float4*)(src + colK + dc);
            *(float4*)&Vs[kr * 68 + dc] = *(const float4*)(src + colV + dc);
        }
        __syncthreads();

        // ---- scores: acc[ri][0]=key kg, acc[ri][1]=key kg+32 ----
        float acc[8][2];
#pragma unroll
        for (int i = 0; i < 8; i++) { acc[i][0] = 0.f; acc[i][1] = 0.f; }

#pragma unroll
        for (int d4 = 0; d4 < HDD; d4 += 4) {
            float4 k0 = *(float4*)&Ks[kg * 68 + d4];
            float4 k1 = *(float4*)&Ks[(kg + 32) * 68 + d4];
#pragma unroll
            for (int ri = 0; ri < 8; ri++) {
                float4 q = *(float4*)&Qs[(8 * w + ri) * 68 + d4];  // broadcast
                acc[ri][0] = fmaf(q.x, k0.x, acc[ri][0]);
                acc[ri][0] = fmaf(q.y, k0.y, acc[ri][0]);
                acc[ri][0] = fmaf(q.z, k0.z, acc[ri][0]);
                acc[ri][0] = fmaf(q.w, k0.w, acc[ri][0]);
                acc[ri][1] = fmaf(q.x, k1.x, acc[ri][1]);
                acc[ri][1] = fmaf(q.y, k1.y, acc[ri][1]);
                acc[ri][1] = fmaf(q.z, k1.z, acc[ri][1]);
                acc[ri][1] = fmaf(q.w, k1.w, acc[ri][1]);
            }
        }

        // ---- online softmax per row (warp-uniform stats) ----
        const int m0 = msk[kt * 64 + kg];
        const int m1 = msk[kt * 64 + kg + 32];
#pragma unroll
        for (int ri = 0; ri < 8; ri++) {
            float s0 = m0 ? -10000.0f : acc[ri][0] * 8.0f;
            float s1 = m1 ? -10000.0f : acc[ri][1] * 8.0f;
            float rm = fmaxf(s0, s1);
#pragma unroll
            for (int off = 1; off < 32; off <<= 1)
                rm = fmaxf(rm, __shfl_xor_sync(0xffffffffu, rm, off));
            float mnew  = fmaxf(m_i[ri], rm);
            float alpha = __expf(m_i[ri] - mnew);   // first tile: exp(-inf)=0
            float p0 = __expf(s0 - mnew);
            float p1 = __expf(s1 - mnew);
            float ps = p0 + p1;
#pragma unroll
            for (int off = 1; off < 32; off <<= 1)
                ps += __shfl_xor_sync(0xffffffffu, ps, off);
            l_i[ri] = l_i[ri] * alpha + ps;
            m_i[ri] = mnew;
            Ps[(8 * w + ri) * 68 + kg]      = p0;
            Ps[(8 * w + ri) * 68 + kg + 32] = p1;
            if (ri == rs) {                 // rescale this lane's O row
#pragma unroll
                for (int j = 0; j < 16; j++) o[j] *= alpha;
            }
        }
        __syncwarp();   // Ps rows are warp-private: no block barrier needed

        // ---- PV: o[c*4+j] += P[row_sub][key] * V[key][dg*4+16c+j] ----
        const int prow = (8 * w + rs) * 68;
#pragma unroll 2
        for (int key = 0; key < 64; key += 4) {
            float4 p = *(float4*)&Ps[prow + key];
#pragma unroll
            for (int c = 0; c < 4; c++) {
                int dcol = dg * 4 + 16 * c;
                float4 v0 = *(float4*)&Vs[(key + 0) * 68 + dcol];
                float4 v1 = *(float4*)&Vs[(key + 1) * 68 + dcol];
                float4 v2 = *(float4*)&Vs[(key + 2) * 68 + dcol];
                float4 v3 = *(float4*)&Vs[(key + 3) * 68 + dcol];
                float* oc = o + c * 4;
                oc[0] = fmaf(p.x, v0.x, oc[0]); oc[1] = fmaf(p.x, v0.y, oc[1]);
                oc[2] = fmaf(p.x, v0.z, oc[2]); oc[3] = fmaf(p.x, v0.w, oc[3]);
                oc[0] = fmaf(p.y, v1.x, oc[0]); oc[1] = fmaf(p.y, v1.y, oc[1]);
                oc[2] = fmaf(p.y, v1.z, oc[2]); oc[3] = fmaf(p.y, v1.w, oc[3]);
                oc[0] = fmaf(p.z, v2.x, oc[0]); oc[1] = fmaf(p.z, v2.y, oc[1]);
                oc[2] = fmaf(p.z, v2.z, oc[2]); oc[3] = fmaf(p.z, v2.w, oc[3]);
                oc[0] = fmaf(p.w, v3.x, oc[0]); oc[1] = fmaf(p.w, v3.y, oc[1]);
                oc[2] = fmaf(p.w, v3.z, oc[2]); oc[3] = fmaf(p.w, v3.w, oc[3]);
            }
        }
    }

    // ---- normalize + write out[b][q0+8w+rs][h*64 + dg*4 + 16c + j] ----
    {
        float inv = 1.0f / l_i[rs];
        size_t base = ((size_t)b * SS + q0 + 8 * w + rs) * HH + h * HDD;
#pragma unroll
        for (int c = 0; c < 4; c++) {
            float4 res;
            res.x = o[c * 4 + 0] * inv;
            res.y = o[c * 4 + 1] * inv;
            res.z = o[c * 4 + 2] * inv;
            res.w = o[c * 4 + 3] * inv;
            *(float4*)(out + base + dg * 4 + 16 * c) = res;
        }
    }
}

// ---------------------------------------------------------------------------
extern "C" void kernel_launch(void* const* d_in, const int* in_sizes, int n_in,
                              void* d_out, int out_size)
{
    const float* hidden = nullptr;
    const int*   amask  = nullptr;
    const float* w_qkv  = nullptr;
    const float* b_qkv  = nullptr;

    for (int i = 0; i < n_in; i++) {
        switch (in_sizes[i]) {
            case 8388608: hidden = (const float*)d_in[i]; break;
            case 8192:    amask  = (const int*)  d_in[i]; break;
            case 3145728: w_qkv  = (const float*)d_in[i]; break;
            case 3072:    b_qkv  = (const float*)d_in[i]; break;
            default: break;
        }
    }
    if (!hidden) hidden = (const float*)d_in[0];
    if (!amask)  amask  = (const int*)  d_in[1];
    if (!w_qkv)  w_qkv  = (const float*)d_in[2];
    if (!b_qkv)  b_qkv  = (const float*)d_in[3];

    float* outp = (float*)d_out;

    dim3 g1(KQKV / 128, (BB * SS) / 128);   // (24, 64)
    qkv_gemm_kernel<<<g1, 256>>>(hidden, w_qkv, b_qkv);

    static int smem_set = 0;
    if (!smem_set) {
        cudaFuncSetAttribute(attn_kernel,
                             cudaFuncAttributeMaxDynamicSharedMemorySize,
                             SMEM_ATTN_BYTES);
        smem_set = 1;
    }
    dim3 g2(SS / 64, NHH, BB);              // (16, 16, 8)
    attn_kernel<<<g2, 256, SMEM_ATTN_BYTES>>>(amask, outp);

    (void)out_size;
}

// round 13
// speedup vs baseline: 2.8175x; 1.3195x over previous
#include <cuda_runtime.h>
#include <math.h>

#define BB  8
#define SS  1024
#define HH  1024
#define NHH 16
#define HDD 64
#define KQKV (3 * HH)   // 3072

// Scratch in plain GEMM-output layout: qkv[m][c], m = b*1024+s,
// c = head*192 + which*64 + d (0=Q,1=K,2=V) — verified correct since R6.
__device__ __align__(16) float g_qkv[(size_t)BB * SS * KQKV];

// ---------------------------------------------------------------------------
// Kernel 1 (unchanged, verified, ~48 TF/s): C = A @ W + bias
// ---------------------------------------------------------------------------
__global__ __launch_bounds__(256, 2)
void qkv_gemm_kernel(const float* __restrict__ A,
                     const float* __restrict__ W,
                     const float* __restrict__ bias)
{
    __shared__ __align__(16) float sA[16][132];  // [k][m]
    __shared__ __align__(16) float sB[16][132];  // [k][n]

    const int tid = threadIdx.x;
    const int tx  = tid & 15;
    const int ty  = tid >> 4;
    const int rBase = blockIdx.y * 128;
    const int cBase = blockIdx.x * 128;

    const int am = tid >> 1;
    const int ac = (tid & 1) * 4;
    const int bk = tid >> 5;
    const int bn = (tid & 31) * 4;

    float acc[8][8];
#pragma unroll
    for (int i = 0; i < 8; i++)
#pragma unroll
        for (int j = 0; j < 8; j++) acc[i][j] = 0.f;

    const float* Arow = A + (size_t)(rBase + am) * HH;

    for (int kt = 0; kt < HH; kt += 16) {
        float4 a0 = *(const float4*)(Arow + kt + ac);
        float4 a1 = *(const float4*)(Arow + kt + ac + 8);
        sA[ac + 0][am] = a0.x;  sA[ac + 1][am] = a0.y;
        sA[ac + 2][am] = a0.z;  sA[ac + 3][am] = a0.w;
        sA[ac + 8][am] = a1.x;  sA[ac + 9][am] = a1.y;
        sA[ac +10][am] = a1.z;  sA[ac +11][am] = a1.w;

        *(float4*)&sB[bk][bn] =
            *(const float4*)(W + (size_t)(kt + bk) * KQKV + cBase + bn);
        *(float4*)&sB[bk + 8][bn] =
            *(const float4*)(W + (size_t)(kt + bk + 8) * KQKV + cBase + bn);
        __syncthreads();

#pragma unroll
        for (int kk = 0; kk < 16; kk++) {
            float4 A0 = *(float4*)&sA[kk][ty * 8];
            float4 A1 = *(float4*)&sA[kk][ty * 8 + 4];
            float4 B0 = *(float4*)&sB[kk][tx * 4];
            float4 B1 = *(float4*)&sB[kk][64 + tx * 4];
            float a[8] = {A0.x, A0.y, A0.z, A0.w, A1.x, A1.y, A1.z, A1.w};
            float b[8] = {B0.x, B0.y, B0.z, B0.w, B1.x, B1.y, B1.z, B1.w};
#pragma unroll
            for (int i = 0; i < 8; i++)
#pragma unroll
                for (int j = 0; j < 8; j++)
                    acc[i][j] = fmaf(a[i], b[j], acc[i][j]);
        }
        __syncthreads();
    }

    float4 bb0 = *(const float4*)(bias + cBase + tx * 4);
    float4 bb1 = *(const float4*)(bias + cBase + 64 + tx * 4);
#pragma unroll
    for (int i = 0; i < 8; i++) {
        size_t m = (size_t)(rBase + ty * 8 + i);
        float4 o0, o1;
        o0.x = acc[i][0] + bb0.x;  o0.y = acc[i][1] + bb0.y;
        o0.z = acc[i][2] + bb0.z;  o0.w = acc[i][3] + bb0.w;
        o1.x = acc[i][4] + bb1.x;  o1.y = acc[i][5] + bb1.y;
        o1.z = acc[i][6] + bb1.z;  o1.w = acc[i][7] + bb1.w;
        *(float4*)(g_qkv + m * KQKV + cBase + tx * 4)      = o0;
        *(float4*)(g_qkv + m * KQKV + cBase + 64 + tx * 4) = o1;
    }
}

// ---------------------------------------------------------------------------
// Kernel 2: flash attention, online softmax, balanced 4x4 lane tiles.
// Block = (b, h, 64 q-rows), 256 thr = 8 warps; warp w owns rows 8w..8w+7.
// Lane = (rg = lane>>4, q4 = lane&15):
//   scores: rows 4rg+i  x keys {q4, q4+16, q4+32, q4+48}   (4 K + 4 Q LDS/64 FFMA)
//   PV    : rows 4rg+i  x cols 4*q4..4*q4+3                (4 P + 4 V LDS/64 FFMA)
// All SMEM patterns conflict-free per quarter-warp phase (bank-verified).
// SMEM: Qs/Ks/Vs/Ps[64][68] + msk[1024] = 73.7 KB -> 3 CTAs/SM.
// ---------------------------------------------------------------------------
#define OFF_Q 0
#define OFF_K (OFF_Q + 64 * 68)
#define OFF_V (OFF_K + 64 * 68)
#define OFF_P (OFF_V + 64 * 68)
#define OFF_M (OFF_P + 64 * 68)
#define SMEM_ATTN_FLOATS (OFF_M + 1024)
#define SMEM_ATTN_BYTES  (SMEM_ATTN_FLOATS * 4)

__global__ __launch_bounds__(256, 3)
void attn_kernel(const int* __restrict__ mask, float* __restrict__ out)
{
    extern __shared__ __align__(16) float sm[];
    float* Qs = sm + OFF_Q;
    float* Ks = sm + OFF_K;
    float* Vs = sm + OFF_V;
    float* Ps = sm + OFF_P;
    int*   msk = (int*)(sm + OFF_M);

    const int tid  = threadIdx.x;
    const int w    = tid >> 5;
    const int lane = tid & 31;
    const int rg   = lane >> 4;   // 0/1: rows 4rg..4rg+3 within warp's 8
    const int q4   = lane & 15;   // key-lane (scores) / d-col group (PV)
    const int q0   = blockIdx.x * 64;
    const int h    = blockIdx.y;
    const int b    = blockIdx.z;

    const size_t rowBase = (size_t)b * SS;
    const int colQ = h * 192;
    const int colK = colQ + 64;
    const int colV = colQ + 128;

    const int rowS = (8 * w + 4 * rg) * 68;   // this lane's first score/PV row

    // ---- load Q tile (64x64, 4 float4/thread) + mask row ----
#pragma unroll
    for (int l = 0; l < 4; l++) {
        int idx = tid + l * 256;
        int qr = idx >> 4;
        int dc = (idx & 15) * 4;
        *(float4*)&Qs[qr * 68 + dc] =
            *(const float4*)(g_qkv + (rowBase + q0 + qr) * KQKV + colQ + dc);
    }
#pragma unroll
    for (int l = 0; l < 4; l++) {
        int idx = tid + l * 256;
        msk[idx] = mask[b * SS + idx];
    }

    float m_i[4], l_i[4], o[4][4];
#pragma unroll
    for (int i = 0; i < 4; i++) {
        m_i[i] = -INFINITY; l_i[i] = 0.f;
#pragma unroll
        for (int j = 0; j < 4; j++) o[i][j] = 0.f;
    }

    for (int kt = 0; kt < SS / 64; kt++) {
        __syncthreads();   // prev-tile K/V readers done; 1st iter: Q/msk visible

#pragma unroll
        for (int l = 0; l < 4; l++) {
            int idx = tid + l * 256;
            int kr = idx >> 4;
            int dc = (idx & 15) * 4;
            const float* src = g_qkv + (rowBase + kt * 64 + kr) * KQKV;
            *(float4*)&Ks[kr * 68 + dc] = *(const float4*)(src + colK + dc);
            *(float4*)&Vs[kr * 68 + dc] = *(const float4*)(src + colV + dc);
        }
        __syncthreads();

        // ---- scores: acc[i][j] = Q[4rg+i] . K[q4+16j] ----
        float acc[4][4];
#pragma unroll
        for (int i = 0; i < 4; i++)
#pragma unroll
            for (int j = 0; j < 4; j++) acc[i][j] = 0.f;

#pragma unroll
        for (int d4 = 0; d4 < HDD; d4 += 4) {
            float4 k[4], q[4];
#pragma unroll
            for (int j = 0; j < 4; j++)
                k[j] = *(float4*)&Ks[(q4 + 16 * j) * 68 + d4];
#pragma unroll
            for (int i = 0; i < 4; i++)
                q[i] = *(float4*)&Qs[rowS + i * 68 + d4];   // phase-broadcast
#pragma unroll
            for (int i = 0; i < 4; i++)
#pragma unroll
                for (int j = 0; j < 4; j++) {
                    acc[i][j] = fmaf(q[i].x, k[j].x, acc[i][j]);
                    acc[i][j] = fmaf(q[i].y, k[j].y, acc[i][j]);
                    acc[i][j] = fmaf(q[i].z, k[j].z, acc[i][j]);
                    acc[i][j] = fmaf(q[i].w, k[j].w, acc[i][j]);
                }
        }

        // ---- online softmax (stats uniform per 16-lane half) ----
        int mj[4];
#pragma unroll
        for (int j = 0; j < 4; j++) mj[j] = msk[kt * 64 + q4 + 16 * j];

#pragma unroll
        for (int i = 0; i < 4; i++) {
            float s[4];
#pragma unroll
            for (int j = 0; j < 4; j++)
                s[j] = mj[j] ? -10000.0f : acc[i][j] * 8.0f;
            float rm = fmaxf(fmaxf(s[0], s[1]), fmaxf(s[2], s[3]));
#pragma unroll
            for (int off = 1; off < 16; off <<= 1)   // stays in 16-lane half
                rm = fmaxf(rm, __shfl_xor_sync(0xffffffffu, rm, off));
            float mnew  = fmaxf(m_i[i], rm);
            float alpha = __expf(m_i[i] - mnew);     // first tile: exp(-inf)=0
            float p[4], ps = 0.f;
#pragma unroll
            for (int j = 0; j < 4; j++) { p[j] = __expf(s[j] - mnew); ps += p[j]; }
#pragma unroll
            for (int off = 1; off < 16; off <<= 1)
                ps += __shfl_xor_sync(0xffffffffu, ps, off);
            l_i[i] = l_i[i] * alpha + ps;
            m_i[i] = mnew;
#pragma unroll
            for (int j = 0; j < 4; j++) {
                Ps[rowS + i * 68 + q4 + 16 * j] = p[j];   // banks distinct/phase
                o[i][j] *= alpha;                          // same rows as scores
            }
        }
        __syncwarp();   // Ps rows warp-private

        // ---- PV: o[i][c] += P[4rg+i][key+jj] * V[key+jj][4*q4+c] ----
#pragma unroll 4
        for (int key = 0; key < 64; key += 4) {
            float4 p[4], v[4];
#pragma unroll
            for (int i = 0; i < 4; i++)
                p[i] = *(float4*)&Ps[rowS + i * 68 + key];   // phase-broadcast
#pragma unroll
            for (int jj = 0; jj < 4; jj++)
                v[jj] = *(float4*)&Vs[(key + jj) * 68 + 4 * q4];
#pragma unroll
            for (int i = 0; i < 4; i++) {
                o[i][0] = fmaf(p[i].x, v[0].x, o[i][0]);
                o[i][1] = fmaf(p[i].x, v[0].y, o[i][1]);
                o[i][2] = fmaf(p[i].x, v[0].z, o[i][2]);
                o[i][3] = fmaf(p[i].x, v[0].w, o[i][3]);
                o[i][0] = fmaf(p[i].y, v[1].x, o[i][0]);
                o[i][1] = fmaf(p[i].y, v[1].y, o[i][1]);
                o[i][2] = fmaf(p[i].y, v[1].z, o[i][2]);
                o[i][3] = fmaf(p[i].y, v[1].w, o[i][3]);
                o[i][0] = fmaf(p[i].z, v[2].x, o[i][0]);
                o[i][1] = fmaf(p[i].z, v[2].y, o[i][1]);
                o[i][2] = fmaf(p[i].z, v[2].z, o[i][2]);
                o[i][3] = fmaf(p[i].z, v[2].w, o[i][3]);
                o[i][0] = fmaf(p[i].w, v[3].x, o[i][0]);
                o[i][1] = fmaf(p[i].w, v[3].y, o[i][1]);
                o[i][2] = fmaf(p[i].w, v[3].z, o[i][2]);
                o[i][3] = fmaf(p[i].w, v[3].w, o[i][3]);
            }
        }
    }

    // ---- normalize + write out[b][q0+8w+4rg+i][h*64 + 4*q4 + c] ----
#pragma unroll
    for (int i = 0; i < 4; i++) {
        float inv = 1.0f / l_i[i];
        float4 res;
        res.x = o[i][0] * inv;
        res.y = o[i][1] * inv;
        res.z = o[i][2] * inv;
        res.w = o[i][3] * inv;
        *(float4*)(out + ((size_t)b * SS + q0 + 8 * w + 4 * rg + i) * HH
                   + h * HDD + 4 * q4) = res;
    }
}

// ---------------------------------------------------------------------------
extern "C" void kernel_launch(void* const* d_in, const int* in_sizes, int n_in,
                              void* d_out, int out_size)
{
    const float* hidden = nullptr;
    const int*   amask  = nullptr;
    const float* w_qkv  = nullptr;
    const float* b_qkv  = nullptr;

    for (int i = 0; i < n_in; i++) {
        switch (in_sizes[i]) {
            case 8388608: hidden = (const float*)d_in[i]; break;
            case 8192:    amask  = (const int*)  d_in[i]; break;
            case 3145728: w_qkv  = (const float*)d_in[i]; break;
            case 3072:    b_qkv  = (const float*)d_in[i]; break;
            default: break;
        }
    }
    if (!hidden) hidden = (const float*)d_in[0];
    if (!amask)  amask  = (const int*)  d_in[1];
    if (!w_qkv)  w_qkv  = (const float*)d_in[2];
    if (!b_qkv)  b_qkv  = (const float*)d_in[3];

    float* outp = (float*)d_out;

    dim3 g1(KQKV / 128, (BB * SS) / 128);   // (24, 64)
    qkv_gemm_kernel<<<g1, 256>>>(hidden, w_qkv, b_qkv);

    static int smem_set = 0;
    if (!smem_set) {
        cudaFuncSetAttribute(attn_kernel,
                             cudaFuncAttributeMaxDynamicSharedMemorySize,
                             SMEM_ATTN_BYTES);
        smem_set = 1;
    }
    dim3 g2(SS / 64, NHH, BB);              // (16, 16, 8)
    attn_kernel<<<g2, 256, SMEM_ATTN_BYTES>>>(amask, outp);

    (void)out_size;
}

// round 14
// speedup vs baseline: 3.9061x; 1.3864x over previous
#include <cuda_runtime.h>
#include <math.h>

#define BB  8
#define SS  1024
#define HH  1024
#define NHH 16
#define HDD 64
#define KQKV (3 * HH)   // 3072

// Scratch in plain GEMM-output layout: qkv[m][c], m = b*1024+s,
// c = head*192 + which*64 + d (0=Q,1=K,2=V) — verified correct since R6.
__device__ __align__(16) float g_qkv[(size_t)BB * SS * KQKV];
// Per-batch compacted unmasked-key indices + counts.
__device__ int g_kidx[BB * SS];
__device__ int g_kcnt[BB];

// ---------------------------------------------------------------------------
// Kernel 0: per-batch mask compaction (keep keys with mask==0).
// Tail slots [cnt,1024) filled with identity so fallback/padding reads are valid.
// ---------------------------------------------------------------------------
__global__ void compact_kernel(const int* __restrict__ mask)
{
    __shared__ int scan[1024];
    const int b = blockIdx.x;
    const int t = threadIdx.x;

    const int keep = (mask[b * SS + t] == 0) ? 1 : 0;
    scan[t] = keep;
    __syncthreads();
#pragma unroll
    for (int off = 1; off < 1024; off <<= 1) {
        int v   = scan[t];
        int add = (t >= off) ? scan[t - off] : 0;
        __syncthreads();
        scan[t] = v + add;
        __syncthreads();
    }
    const int total = scan[1023];
    if (keep) g_kidx[b * SS + scan[t] - 1] = t;   // [0,total)
    if (t >= total) g_kidx[b * SS + t] = t;       // [total,1024): identity fill
    if (t == 0) g_kcnt[b] = total;
}

// ---------------------------------------------------------------------------
// Kernel 1: C[8192,3072] = A[8192,1024] @ W[1024,3072] + bias
// 128x128 tile, BK=16, 256 threads, 8x8 microtile, DOUBLE-BUFFERED smem.
// ---------------------------------------------------------------------------
__global__ __launch_bounds__(256, 2)
void qkv_gemm_kernel(const float* __restrict__ A,
                     const float* __restrict__ W,
                     const float* __restrict__ bias)
{
    __shared__ __align__(16) float sA[2][16][132];  // [buf][k][m]
    __shared__ __align__(16) float sB[2][16][132];  // [buf][k][n]

    const int tid = threadIdx.x;
    const int tx  = tid & 15;
    const int ty  = tid >> 4;
    const int rBase = blockIdx.y * 128;
    const int cBase = blockIdx.x * 128;

    const int am = tid >> 1;
    const int ac = (tid & 1) * 4;
    const int bk = tid >> 5;
    const int bn = (tid & 31) * 4;

    float acc[8][8];
#pragma unroll
    for (int i = 0; i < 8; i++)
#pragma unroll
        for (int j = 0; j < 8; j++) acc[i][j] = 0.f;

    const float* Arow = A + (size_t)(rBase + am) * HH;

    // Preload kt=0 into buffer 0
    {
        float4 a0 = *(const float4*)(Arow + ac);
        float4 a1 = *(const float4*)(Arow + ac + 8);
        sA[0][ac + 0][am] = a0.x;  sA[0][ac + 1][am] = a0.y;
        sA[0][ac + 2][am] = a0.z;  sA[0][ac + 3][am] = a0.w;
        sA[0][ac + 8][am] = a1.x;  sA[0][ac + 9][am] = a1.y;
        sA[0][ac +10][am] = a1.z;  sA[0][ac +11][am] = a1.w;
        *(float4*)&sB[0][bk][bn] =
            *(const float4*)(W + (size_t)bk * KQKV + cBase + bn);
        *(float4*)&sB[0][bk + 8][bn] =
            *(const float4*)(W + (size_t)(bk + 8) * KQKV + cBase + bn);
    }
    __syncthreads();

    int cur = 0;
    for (int kt = 0; kt < HH; kt += 16) {
        const bool has = (kt + 16 < HH);
        float4 a0n, a1n, b0n, b1n;
        if (has) {     // issue next tile's LDGs early; consumed after compute
            a0n = *(const float4*)(Arow + kt + 16 + ac);
            a1n = *(const float4*)(Arow + kt + 16 + ac + 8);
            b0n = *(const float4*)(W + (size_t)(kt + 16 + bk) * KQKV + cBase + bn);
            b1n = *(const float4*)(W + (size_t)(kt + 24 + bk) * KQKV + cBase + bn);
        }

#pragma unroll
        for (int kk = 0; kk < 16; kk++) {
            float4 A0 = *(float4*)&sA[cur][kk][ty * 8];
            float4 A1 = *(float4*)&sA[cur][kk][ty * 8 + 4];
            float4 B0 = *(float4*)&sB[cur][kk][tx * 4];
            float4 B1 = *(float4*)&sB[cur][kk][64 + tx * 4];
            float a[8] = {A0.x, A0.y, A0.z, A0.w, A1.x, A1.y, A1.z, A1.w};
            float b[8] = {B0.x, B0.y, B0.z, B0.w, B1.x, B1.y, B1.z, B1.w};
#pragma unroll
            for (int i = 0; i < 8; i++)
#pragma unroll
                for (int j = 0; j < 8; j++)
                    acc[i][j] = fmaf(a[i], b[j], acc[i][j]);
        }

        if (has) {
            const int nxt = cur ^ 1;
            sA[nxt][ac + 0][am] = a0n.x;  sA[nxt][ac + 1][am] = a0n.y;
            sA[nxt][ac + 2][am] = a0n.z;  sA[nxt][ac + 3][am] = a0n.w;
            sA[nxt][ac + 8][am] = a1n.x;  sA[nxt][ac + 9][am] = a1n.y;
            sA[nxt][ac +10][am] = a1n.z;  sA[nxt][ac +11][am] = a1n.w;
            *(float4*)&sB[nxt][bk][bn]     = b0n;
            *(float4*)&sB[nxt][bk + 8][bn] = b1n;
        }
        __syncthreads();
        cur ^= 1;
    }

    float4 bb0 = *(const float4*)(bias + cBase + tx * 4);
    float4 bb1 = *(const float4*)(bias + cBase + 64 + tx * 4);
#pragma unroll
    for (int i = 0; i < 8; i++) {
        size_t m = (size_t)(rBase + ty * 8 + i);
        float4 o0, o1;
        o0.x = acc[i][0] + bb0.x;  o0.y = acc[i][1] + bb0.y;
        o0.z = acc[i][2] + bb0.z;  o0.w = acc[i][3] + bb0.w;
        o1.x = acc[i][4] + bb1.x;  o1.y = acc[i][5] + bb1.y;
        o1.z = acc[i][6] + bb1.z;  o1.w = acc[i][7] + bb1.w;
        *(float4*)(g_qkv + m * KQKV + cBase + tx * 4)      = o0;
        *(float4*)(g_qkv + m * KQKV + cBase + 64 + tx * 4) = o1;
    }
}

// ---------------------------------------------------------------------------
// Kernel 2: flash attention over COMPACTED keys (masked keys contribute
// exactly 0 in fp32: expf(-10000-max) underflows to 0 — bit-exact skip).
// Block = (b, h, 64 q-rows), 256 thr = 8 warps; warp w owns rows 8w..8w+7.
// Lane = (rg = lane>>4, q4 = lane&15): balanced 4x4 tiles (R13-verified).
// Pad slots (pos >= cnt) get score -1e30 -> p = 0. am-case: equal scores
// over identity list -> uniform probs (reference all-masked semantics).
// SMEM: Qs/Ks/Vs/Ps[64][68] + kidx[1024] = 73.7 KB -> 3 CTAs/SM.
// ---------------------------------------------------------------------------
#define OFF_Q 0
#define OFF_K (OFF_Q + 64 * 68)
#define OFF_V (OFF_K + 64 * 68)
#define OFF_P (OFF_V + 64 * 68)
#define OFF_I (OFF_P + 64 * 68)
#define SMEM_ATTN_FLOATS (OFF_I + 1024)
#define SMEM_ATTN_BYTES  (SMEM_ATTN_FLOATS * 4)

__global__ __launch_bounds__(256, 3)
void attn_kernel(float* __restrict__ out)
{
    extern __shared__ __align__(16) float sm[];
    float* Qs = sm + OFF_Q;
    float* Ks = sm + OFF_K;
    float* Vs = sm + OFF_V;
    float* Ps = sm + OFF_P;
    int*   kidx = (int*)(sm + OFF_I);

    const int tid  = threadIdx.x;
    const int w    = tid >> 5;
    const int lane = tid & 31;
    const int rg   = lane >> 4;
    const int q4   = lane & 15;
    const int q0   = blockIdx.x * 64;
    const int h    = blockIdx.y;
    const int b    = blockIdx.z;

    const size_t rowBase = (size_t)b * SS;
    const int colQ = h * 192;
    const int colK = colQ + 64;
    const int colV = colQ + 128;

    const int cnt_raw = g_kcnt[b];
    const bool am_all = (cnt_raw == 0);          // all keys masked (degenerate)
    const int cnt = am_all ? SS : cnt_raw;
    const int nkt = (cnt + 63) >> 6;

    const int rowS = (8 * w + 4 * rg) * 68;

    // ---- load Q tile + compacted index list ----
#pragma unroll
    for (int l = 0; l < 4; l++) {
        int idx = tid + l * 256;
        int qr = idx >> 4;
        int dc = (idx & 15) * 4;
        *(float4*)&Qs[qr * 68 + dc] =
            *(const float4*)(g_qkv + (rowBase + q0 + qr) * KQKV + colQ + dc);
    }
#pragma unroll
    for (int l = 0; l < 4; l++) {
        int idx = tid + l * 256;
        kidx[idx] = g_kidx[b * SS + idx];
    }

    float m_i[4], l_i[4], o[4][4];
#pragma unroll
    for (int i = 0; i < 4; i++) {
        m_i[i] = -INFINITY; l_i[i] = 0.f;
#pragma unroll
        for (int j = 0; j < 4; j++) o[i][j] = 0.f;
    }

    for (int kt = 0; kt < nkt; kt++) {
        __syncthreads();   // prev-tile K/V readers done; 1st iter: Q/kidx visible

        // gather K,V tiles through the compacted index list
#pragma unroll
        for (int l = 0; l < 4; l++) {
            int idx = tid + l * 256;
            int kr = idx >> 4;
            int dc = (idx & 15) * 4;
            int gk = kidx[kt * 64 + kr];
            const float* src = g_qkv + (rowBase + gk) * KQKV;
            *(float4*)&Ks[kr * 68 + dc] = *(const float4*)(src + colK + dc);
            *(float4*)&Vs[kr * 68 + dc] = *(const float4*)(src + colV + dc);
        }
        __syncthreads();

        // ---- scores: acc[i][j] = Q[4rg+i] . K[q4+16j] ----
        float acc[4][4];
#pragma unroll
        for (int i = 0; i < 4; i++)
#pragma unroll
            for (int j = 0; j < 4; j++) acc[i][j] = 0.f;

#pragma unroll
        for (int d4 = 0; d4 < HDD; d4 += 4) {
            float4 k[4], q[4];
#pragma unroll
            for (int j = 0; j < 4; j++)
                k[j] = *(float4*)&Ks[(q4 + 16 * j) * 68 + d4];
#pragma unroll
            for (int i = 0; i < 4; i++)
                q[i] = *(float4*)&Qs[rowS + i * 68 + d4];
#pragma unroll
            for (int i = 0; i < 4; i++)
#pragma unroll
                for (int j = 0; j < 4; j++) {
                    acc[i][j] = fmaf(q[i].x, k[j].x, acc[i][j]);
                    acc[i][j] = fmaf(q[i].y, k[j].y, acc[i][j]);
                    acc[i][j] = fmaf(q[i].z, k[j].z, acc[i][j]);
                    acc[i][j] = fmaf(q[i].w, k[j].w, acc[i][j]);
                }
        }

        // pad predicates: compact position >= cnt -> p must be 0
        bool pad[4];
#pragma unroll
        for (int j = 0; j < 4; j++)
            pad[j] = (kt * 64 + q4 + 16 * j) >= cnt;

#pragma unroll
        for (int i = 0; i < 4; i++) {
            float s[4];
#pragma unroll
            for (int j = 0; j < 4; j++) {
                float v = am_all ? 0.f : acc[i][j] * 8.0f;   // am: equal scores
                s[j] = pad[j] ? -1e30f : v;
            }
            float rm = fmaxf(fmaxf(s[0], s[1]), fmaxf(s[2], s[3]));
#pragma unroll
            for (int off = 1; off < 16; off <<= 1)
                rm = fmaxf(rm, __shfl_xor_sync(0xffffffffu, rm, off));
            float mnew  = fmaxf(m_i[i], rm);
            float alpha = __expf(m_i[i] - mnew);
            float p[4], ps = 0.f;
#pragma unroll
            for (int j = 0; j < 4; j++) { p[j] = __expf(s[j] - mnew); ps += p[j]; }
#pragma unroll
            for (int off = 1; off < 16; off <<= 1)
                ps += __shfl_xor_sync(0xffffffffu, ps, off);
            l_i[i] = l_i[i] * alpha + ps;
            m_i[i] = mnew;
#pragma unroll
            for (int j = 0; j < 4; j++) {
                Ps[rowS + i * 68 + q4 + 16 * j] = p[j];
                o[i][j] *= alpha;
            }
        }
        __syncwarp();   // Ps rows warp-private

        // ---- PV: o[i][c] += P[4rg+i][key+jj] * V[key+jj][4*q4+c] ----
#pragma unroll 4
        for (int key = 0; key < 64; key += 4) {
            float4 p[4], v[4];
#pragma unroll
            for (int i = 0; i < 4; i++)
                p[i] = *(float4*)&Ps[rowS + i * 68 + key];
#pragma unroll
            for (int jj = 0; jj < 4; jj++)
                v[jj] = *(float4*)&Vs[(key + jj) * 68 + 4 * q4];
#pragma unroll
            for (int i = 0; i < 4; i++) {
                o[i][0] = fmaf(p[i].x, v[0].x, o[i][0]);
                o[i][1] = fmaf(p[i].x, v[0].y, o[i][1]);
                o[i][2] = fmaf(p[i].x, v[0].z, o[i][2]);
                o[i][3] = fmaf(p[i].x, v[0].w, o[i][3]);
                o[i][0] = fmaf(p[i].y, v[1].x, o[i][0]);
                o[i][1] = fmaf(p[i].y, v[1].y, o[i][1]);
                o[i][2] = fmaf(p[i].y, v[1].z, o[i][2]);
                o[i][3] = fmaf(p[i].y, v[1].w, o[i][3]);
                o[i][0] = fmaf(p[i].z, v[2].x, o[i][0]);
                o[i][1] = fmaf(p[i].z, v[2].y, o[i][1]);
                o[i][2] = fmaf(p[i].z, v[2].z, o[i][2]);
                o[i][3] = fmaf(p[i].z, v[2].w, o[i][3]);
                o[i][0] = fmaf(p[i].w, v[3].x, o[i][0]);
                o[i][1] = fmaf(p[i].w, v[3].y, o[i][1]);
                o[i][2] = fmaf(p[i].w, v[3].z, o[i][2]);
                o[i][3] = fmaf(p[i].w, v[3].w, o[i][3]);
            }
        }
    }

    // ---- normalize + write out[b][q0+8w+4rg+i][h*64 + 4*q4 + c] ----
#pragma unroll
    for (int i = 0; i < 4; i++) {
        float inv = 1.0f / l_i[i];
        float4 res;
        res.x = o[i][0] * inv;
        res.y = o[i][1] * inv;
        res.z = o[i][2] * inv;
        res.w = o[i][3] * inv;
        *(float4*)(out + ((size_t)b * SS + q0 + 8 * w + 4 * rg + i) * HH
                   + h * HDD + 4 * q4) = res;
    }
}

// ---------------------------------------------------------------------------
extern "C" void kernel_launch(void* const* d_in, const int* in_sizes, int n_in,
                              void* d_out, int out_size)
{
    const float* hidden = nullptr;
    const int*   amask  = nullptr;
    const float* w_qkv  = nullptr;
    const float* b_qkv  = nullptr;

    for (int i = 0; i < n_in; i++) {
        switch (in_sizes[i]) {
            case 8388608: hidden = (const float*)d_in[i]; break;
            case 8192:    amask  = (const int*)  d_in[i]; break;
            case 3145728: w_qkv  = (const float*)d_in[i]; break;
            case 3072:    b_qkv  = (const float*)d_in[i]; break;
            default: break;
        }
    }
    if (!hidden) hidden = (const float*)d_in[0];
    if (!amask)  amask  = (const int*)  d_in[1];
    if (!w_qkv)  w_qkv  = (const float*)d_in[2];
    if (!b_qkv)  b_qkv  = (const float*)d_in[3];

    float* outp = (float*)d_out;

    compact_kernel<<<BB, 1024>>>(amask);

    dim3 g1(KQKV / 128, (BB * SS) / 128);   // (24, 64)
    qkv_gemm_kernel<<<g1, 256>>>(hidden, w_qkv, b_qkv);

    static int smem_set = 0;
    if (!smem_set) {
        cudaFuncSetAttribute(attn_kernel,
                             cudaFuncAttributeMaxDynamicSharedMemorySize,
                             SMEM_ATTN_BYTES);
        smem_set = 1;
    }
    dim3 g2(SS / 64, NHH, BB);              // (16, 16, 8)
    attn_kernel<<<g2, 256, SMEM_ATTN_BYTES>>>(outp);

    (void)out_size;
}